// round 9
// baseline (speedup 1.0000x reference)
#include <cuda_runtime.h>

// out[e] = sigmoid( dot( x[src[e], 0:128], x[dst[e], 128:256] ) )
// x: [100000, 256] fp32 (102 MB — nearly fits the 126 MB L2).
// edge_label_index: [2, N_EDGES] int32 on device.
//
// 8 edges per warp, MLP=16 gather LDG.128s per lane.
// x gathers carry an L2::evict_last createpolicy (table stays L2-resident);
// index loads carry evict_first (pure streaming).
// Merging butterfly: 16 SHFLs reduce all 8 edge dots at once; lane l ends
// holding edge (l & 7) -> lanes 0-7 do parallel sigmoids + one 32B store.

#define HIDDEN 256
#define HALF   128
#define EPW    8     // edges per warp

__device__ __forceinline__ float sigmoidf(float v)
{
    return 1.0f / (1.0f + __expf(-v));
}

__device__ __forceinline__ unsigned long long make_policy_evict_last()
{
    unsigned long long pol;
    asm("createpolicy.fractional.L2::evict_last.b64 %0, 1.0;" : "=l"(pol));
    return pol;
}

__device__ __forceinline__ unsigned long long make_policy_evict_first()
{
    unsigned long long pol;
    asm("createpolicy.fractional.L2::evict_first.b64 %0, 1.0;" : "=l"(pol));
    return pol;
}

// x-table gather: keep resident in L2 via cache-hint policy.
__device__ __forceinline__ float4 ldg_x(const float4* p, unsigned long long pol)
{
    float4 v;
    asm("ld.global.nc.L2::cache_hint.v4.f32 {%0,%1,%2,%3}, [%4], %5;"
        : "=f"(v.x), "=f"(v.y), "=f"(v.z), "=f"(v.w) : "l"(p), "l"(pol));
    return v;
}

// streaming index load: evict_first so it never displaces the x table.
__device__ __forceinline__ int4 ldg_idx(const int4* p, unsigned long long pol)
{
    int4 v;
    asm("ld.global.nc.L2::cache_hint.v4.s32 {%0,%1,%2,%3}, [%4], %5;"
        : "=r"(v.x), "=r"(v.y), "=r"(v.z), "=r"(v.w) : "l"(p), "l"(pol));
    return v;
}

__global__ __launch_bounds__(256)
void edge_dot_sigmoid_kernel(const float* __restrict__ x,
                             const int* __restrict__ eidx,
                             float* __restrict__ out,
                             int n_edges)
{
    int warp = (blockIdx.x * blockDim.x + threadIdx.x) >> 5;
    int lane = threadIdx.x & 31;
    int base = warp * EPW;
    if (base >= n_edges) return;

    unsigned long long pol_keep   = make_policy_evict_last();

    if (base + EPW <= n_edges) {
        unsigned long long pol_stream = make_policy_evict_first();

        // Warp-uniform vector index loads (16B requests, evict_first).
        int4 s0 = ldg_idx(reinterpret_cast<const int4*>(eidx + base),           pol_stream);
        int4 s1 = ldg_idx(reinterpret_cast<const int4*>(eidx + base + 4),       pol_stream);
        int4 d0 = ldg_idx(reinterpret_cast<const int4*>(eidx + n_edges + base), pol_stream);
        int4 d1 = ldg_idx(reinterpret_cast<const int4*>(eidx + n_edges + base + 4), pol_stream);
        int s[EPW] = {s0.x, s0.y, s0.z, s0.w, s1.x, s1.y, s1.z, s1.w};
        int d[EPW] = {d0.x, d0.y, d0.z, d0.w, d1.x, d1.y, d1.z, d1.w};

        // Issue all 16 gathers before any math (MLP=16 per lane, evict_last).
        float4 a[EPW], b[EPW];
        #pragma unroll
        for (int k = 0; k < EPW; k++)
            a[k] = ldg_x(reinterpret_cast<const float4*>(
                       x + (long long)s[k] * HIDDEN) + lane, pol_keep);
        #pragma unroll
        for (int k = 0; k < EPW; k++)
            b[k] = ldg_x(reinterpret_cast<const float4*>(
                       x + (long long)d[k] * HIDDEN + HALF) + lane, pol_keep);

        float v[EPW];
        #pragma unroll
        for (int k = 0; k < EPW; k++)
            v[k] = a[k].x * b[k].x + a[k].y * b[k].y
                 + a[k].z * b[k].z + a[k].w * b[k].w;

        // Merging butterfly: 8 -> 4 -> 2 -> 1 arrays, then finish the tree.
        float m0[4];
        #pragma unroll
        for (int k = 0; k < 4; k++) {
            float e0 = v[2*k]   + __shfl_xor_sync(0xffffffffu, v[2*k],   1);
            float e1 = v[2*k+1] + __shfl_xor_sync(0xffffffffu, v[2*k+1], 1);
            m0[k] = (lane & 1) ? e1 : e0;
        }
        float m1[2];
        #pragma unroll
        for (int k = 0; k < 2; k++) {
            float e0 = m0[2*k]   + __shfl_xor_sync(0xffffffffu, m0[2*k],   2);
            float e1 = m0[2*k+1] + __shfl_xor_sync(0xffffffffu, m0[2*k+1], 2);
            m1[k] = (lane & 2) ? e1 : e0;
        }
        float e0 = m1[0] + __shfl_xor_sync(0xffffffffu, m1[0], 4);
        float e1 = m1[1] + __shfl_xor_sync(0xffffffffu, m1[1], 4);
        float m2 = (lane & 4) ? e1 : e0;
        m2 += __shfl_xor_sync(0xffffffffu, m2, 8);
        m2 += __shfl_xor_sync(0xffffffffu, m2, 16);
        // lane l now holds the full dot for edge (l & 7).

        if (lane < EPW)
            out[base + lane] = sigmoidf(m2);
    } else {
        // Tail: up to EPW-1 edges, scalar path.
        for (int e = base; e < n_edges; e++) {
            int s = __ldg(&eidx[e]);
            int d = __ldg(&eidx[n_edges + e]);
            float4 a = ldg_x(reinterpret_cast<const float4*>(
                           x + (long long)s * HIDDEN) + lane, pol_keep);
            float4 b = ldg_x(reinterpret_cast<const float4*>(
                           x + (long long)d * HIDDEN + HALF) + lane, pol_keep);
            float dot = a.x * b.x + a.y * b.y + a.z * b.z + a.w * b.w;
            #pragma unroll
            for (int off = 16; off > 0; off >>= 1)
                dot += __shfl_xor_sync(0xffffffffu, dot, off);
            if (lane == 0)
                out[e] = sigmoidf(dot);
        }
    }
}

extern "C" void kernel_launch(void* const* d_in, const int* in_sizes, int n_in,
                              void* d_out, int out_size)
{
    const float* x    = (const float*)d_in[0];
    const int*   eidx = (const int*)d_in[1];
    float*       out  = (float*)d_out;

    int n_edges = in_sizes[1] / 2;   // edge_label_index has 2*N_EDGES elements

    const int threads = 256;                       // 8 warps/block
    int warps_per_block = threads / 32;
    int edges_per_block = warps_per_block * EPW;
    int blocks = (n_edges + edges_per_block - 1) / edges_per_block;

    edge_dot_sigmoid_kernel<<<blocks, threads>>>(x, eidx, out, n_edges);
}